// round 16
// baseline (speedup 1.0000x reference)
#include <cuda_runtime.h>
#include <math.h>
#include <stdint.h>

#define B_SZ   128
#define HD     1024
#define FHH    24
#define FWW    48
#define NPAIR  (FHH * FWW)       // 1152
#define VSPLIT 18
#define PPB    (NPAIR / VSPLIT)  // 64
#define VBLKS  (VSPLIT * B_SZ)   // 2304
#define NSLOT  12                // 4 inp-half + 8 attn-half split-K slots

// SIMT body smem (fused kernel)
#define SROW 68
#define SSTG (16 * SROW)
#define SHSZ (4 * SSTG)

// cp.async mma body smem: stage = A(64x16) + B(64x16), row stride 20 words
#define NST  4
#define AROW 20
#define ASTG (64 * AROW)         // 1280 words per operand stage
#define PSTG (2 * ASTG)          // 2560 words per stage
#define MMSH (NST * PSTG)        // 10240 words = 40 KB

// Scratch (device globals; no allocation allowed)
__device__ float g_p1[8 * B_SZ * 2048];        // GEMM1 split-K partials
__device__ float g_pc[NSLOT * B_SZ * 1024];    // GEMM_C split-K partials
__device__ float g_wp[B_SZ * NPAIR];           // normalized Gaussian weights
__device__ float g_attn[B_SZ * HD];            // attention output
__device__ int   g_sem[32];                    // per-tile split-K semaphores

// ---------------------------------------------------------------------------
// mma / cp.async helpers. NOTE: tf32 operands are fed RAW fp32 bits — the
// HMMA.TF32 datapath reads only the 19 tf32 bits (truncation rounding);
// removes the cvt.rna from the inner loop.
// ---------------------------------------------------------------------------
__device__ __forceinline__ void mma16x8x8(
    float& c0, float& c1, float& c2, float& c3,
    uint32_t a0, uint32_t a1, uint32_t a2, uint32_t a3,
    uint32_t b0, uint32_t b1)
{
    asm volatile(
        "mma.sync.aligned.m16n8k8.row.col.f32.tf32.tf32.f32 "
        "{%0,%1,%2,%3}, {%4,%5,%6,%7}, {%8,%9}, {%0,%1,%2,%3};"
        : "+f"(c0), "+f"(c1), "+f"(c2), "+f"(c3)
        : "r"(a0), "r"(a1), "r"(a2), "r"(a3), "r"(b0), "r"(b1));
}

__device__ __forceinline__ void cp16(uint32_t dst, const void* src) {
    asm volatile("cp.async.ca.shared.global [%0], [%1], 16;\n"
                 :: "r"(dst), "l"(src));
}
#define CP_COMMIT() asm volatile("cp.async.commit_group;\n" ::)
#define CP_WAIT2()  asm volatile("cp.async.wait_group 2;\n" ::)

// ---------------------------------------------------------------------------
// MMA (tf32) 64x64 tile GEMM, BK=16, 256 threads (8 warps: 4m x 2n),
// 4-stage cp.async pipeline (3 groups in flight). Raw fp32 in smem; raw-bit
// tf32 fragments (no cvt).
// ---------------------------------------------------------------------------
__device__ __forceinline__ void gemm_body_mma(
    const float* __restrict__ A,  int lda,
    const float* __restrict__ Bw, int ldb,
    float* __restrict__ outp,     int ldo,
    int m0, int n0, int kbeg, int kend, float* sh)
{
    const int t    = threadIdx.x;
    const int lane = t & 31;
    const int warp = t >> 5;
    const int gid  = lane >> 2;     // 0..7
    const int tig  = lane & 3;      // 0..3
    const int wm   = warp & 3;      // m tile: rows wm*16..+15
    const int wn   = warp >> 2;     // n tile: cols wn*32..+31
    const int lr   = t >> 2;        // 0..63 load row
    const int lc   = (t & 3) << 2;  // 0,4,8,12 load k

    const uint32_t sbase = (uint32_t)__cvta_generic_to_shared(sh);
    const float* Ap = A  + (size_t)(m0 + lr) * lda + lc;
    const float* Bp = Bw + (size_t)(n0 + lr) * ldb + lc;
    const int nch = (kend - kbeg) >> 4;

    auto issue = [&](int c) {
        if (c < nch) {
            int st = c & (NST - 1);
            uint32_t da = sbase + (uint32_t)(st * PSTG + lr * AROW + lc) * 4u;
            uint32_t db = da + (uint32_t)ASTG * 4u;
            int kn = kbeg + (c << 4);
            cp16(da, Ap + kn);
            cp16(db, Bp + kn);
        }
        CP_COMMIT();
    };

    issue(0); issue(1); issue(2);

    float acc[4][4] = {};   // [ntile][c0..c3]

    for (int c = 0; c < nch; c++) {
        CP_WAIT2();
        __syncthreads();

        const uint32_t* Ac = (const uint32_t*)(sh + (c & (NST - 1)) * PSTG);
        const uint32_t* Bc = Ac + ASTG;
        const int am0 = (wm * 16 + gid) * AROW;
        const int am1 = (wm * 16 + gid + 8) * AROW;

        #pragma unroll
        for (int ks = 0; ks < 2; ks++) {
            const int kk = ks << 3;
            uint32_t a0 = Ac[am0 + kk + tig];
            uint32_t a1 = Ac[am1 + kk + tig];
            uint32_t a2 = Ac[am0 + kk + tig + 4];
            uint32_t a3 = Ac[am1 + kk + tig + 4];
            #pragma unroll
            for (int nt = 0; nt < 4; nt++) {
                const int bn = (wn * 32 + nt * 8 + gid) * AROW;
                uint32_t b0 = Bc[bn + kk + tig];
                uint32_t b1 = Bc[bn + kk + tig + 4];
                mma16x8x8(acc[nt][0], acc[nt][1], acc[nt][2], acc[nt][3],
                          a0, a1, a2, a3, b0, b1);
            }
        }
        __syncthreads();
        issue(c + 3);
    }

    #pragma unroll
    for (int nt = 0; nt < 4; nt++) {
        float* orow = outp + (size_t)(m0 + wm*16 + gid) * ldo
                           + n0 + wn*32 + nt*8 + tig*2;
        *(float2*)orow              = make_float2(acc[nt][0], acc[nt][1]);
        *(float2*)(orow + 8 * ldo)  = make_float2(acc[nt][2], acc[nt][3]);
    }
}

// ---------------------------------------------------------------------------
// SIMT fp32 64x64 GEMM body (fused inp-half role; hidden under V stream).
// ---------------------------------------------------------------------------
__device__ __forceinline__ void gemm_body(
    const float* __restrict__ A,  int lda,
    const float* __restrict__ Bw, int ldb,
    float* __restrict__ outp,     int ldo,
    int m0, int n0, int kbeg, int kend, float* sh)
{
    const int t  = threadIdx.x;
    const int tx = t & 15;
    const int ty = t >> 4;
    const int lr = t >> 2;
    const int lc = (t & 3) << 2;

    float* As = sh;
    float* Bs = sh + 2 * SSTG;

    const float* Ap = A  + (size_t)(m0 + lr) * lda + lc;
    const float* Bp = Bw + (size_t)(n0 + lr) * ldb + lc;

    float4 ra = *(const float4*)(Ap + kbeg);
    float4 rb = *(const float4*)(Bp + kbeg);

    As[(lc+0)*SROW + lr] = ra.x;
    As[(lc+1)*SROW + lr] = ra.y;
    As[(lc+2)*SROW + lr] = ra.z;
    As[(lc+3)*SROW + lr] = ra.w;
    Bs[(lc+0)*SROW + lr] = rb.x;
    Bs[(lc+1)*SROW + lr] = rb.y;
    Bs[(lc+2)*SROW + lr] = rb.z;
    Bs[(lc+3)*SROW + lr] = rb.w;
    __syncthreads();

    float acc[4][4] = {};
    const int nch = (kend - kbeg) >> 4;

    for (int c = 0; c < nch; c++) {
        if (c + 1 < nch) {
            int kn = kbeg + ((c + 1) << 4);
            ra = *(const float4*)(Ap + kn);
            rb = *(const float4*)(Bp + kn);
        }
        const float* Ac = As + (c & 1) * SSTG;
        const float* Bc = Bs + (c & 1) * SSTG;
        #pragma unroll
        for (int kk = 0; kk < 16; kk++) {
            float4 av = *(const float4*)&Ac[kk * SROW + (ty << 2)];
            float4 bv = *(const float4*)&Bc[kk * SROW + (tx << 2)];
            float ar[4] = {av.x, av.y, av.z, av.w};
            float br[4] = {bv.x, bv.y, bv.z, bv.w};
            #pragma unroll
            for (int i = 0; i < 4; i++)
                #pragma unroll
                for (int j = 0; j < 4; j++)
                    acc[i][j] += ar[i] * br[j];
        }
        if (c + 1 < nch) {
            const int nx = ((c + 1) & 1) * SSTG;
            As[nx + (lc+0)*SROW + lr] = ra.x;
            As[nx + (lc+1)*SROW + lr] = ra.y;
            As[nx + (lc+2)*SROW + lr] = ra.z;
            As[nx + (lc+3)*SROW + lr] = ra.w;
            Bs[nx + (lc+0)*SROW + lr] = rb.x;
            Bs[nx + (lc+1)*SROW + lr] = rb.y;
            Bs[nx + (lc+2)*SROW + lr] = rb.z;
            Bs[nx + (lc+3)*SROW + lr] = rb.w;
            __syncthreads();
        }
    }

    #pragma unroll
    for (int i = 0; i < 4; i++) {
        float* orow = outp + (size_t)(m0 + (ty << 2) + i) * ldo + n0 + (tx << 2);
        *(float4*)orow = make_float4(acc[i][0], acc[i][1], acc[i][2], acc[i][3]);
    }
}

// ---------------------------------------------------------------------------
// GEMM1 (tf32 mma + cp.async): partials of hid @ W1^T.
// grid (32 n, 2 m, 8 ks), K=128 each.
// ---------------------------------------------------------------------------
__global__ void __launch_bounds__(256) gemm1_kernel(
    const float* __restrict__ hid, const float* __restrict__ W1)
{
    __shared__ float sh[MMSH];
    int ks = blockIdx.z;
    gemm_body_mma(hid, 1024, W1, 1024,
                  g_p1 + (size_t)ks * (B_SZ * 2048), 2048,
                  blockIdx.y * 64, blockIdx.x * 64,
                  ks * 128, ks * 128 + 128, sh);
}

// ---------------------------------------------------------------------------
// Align: t = tanh(sum 8 partials + b1); algn = sigmoid(t @ W2^T + b2);
// -> normalized separable Gaussian weights. Also zeros g_attn. grid 128.
// ---------------------------------------------------------------------------
__global__ void __launch_bounds__(128) align_kernel(
    const float* __restrict__ b1,
    const float* __restrict__ W2, const float* __restrict__ b2)
{
    int b = blockIdx.x;
    int t = threadIdx.x;

    float p0 = 0.f, p1 = 0.f;
    for (int n = t; n < 2048; n += 128) {
        float s = b1[n];
        #pragma unroll
        for (int sp = 0; sp < 8; sp++)
            s += g_p1[(size_t)sp * (B_SZ * 2048) + (size_t)b * 2048 + n];
        float tv = tanhf(s);
        p0 += tv * W2[n];
        p1 += tv * W2[2048 + n];
    }
    #pragma unroll
    for (int o = 16; o > 0; o >>= 1) {
        p0 += __shfl_down_sync(0xffffffffu, p0, o);
        p1 += __shfl_down_sync(0xffffffffu, p1, o);
    }
    __shared__ float r0[4], r1[4];
    int w = t >> 5, l = t & 31;
    if (l == 0) { r0[w] = p0; r1[w] = p1; }
    __syncthreads();

    __shared__ float cxy[2];
    if (t == 0) {
        float s0 = r0[0] + r0[1] + r0[2] + r0[3] + b2[0];
        float s1 = r1[0] + r1[1] + r1[2] + r1[3] + b2[1];
        cxy[0] = (1.f / (1.f + expf(-s0))) * (float)FWW;   // x0
        cxy[1] = (1.f / (1.f + expf(-s1))) * (float)FHH;   // y0
    }
    __syncthreads();

    __shared__ float axv[FWW], ayv[FHH];
    float x0 = cxy[0], y0 = cxy[1];
    if (t < FWW) { float d = (float)t - x0; axv[t] = expf(-d * d * (1.f / 32.f)); }
    if (t >= 64 && t < 64 + FHH) {
        int r = t - 64; float d = (float)r - y0; ayv[r] = expf(-d * d * (1.f / 32.f));
    }
    __syncthreads();

    __shared__ float inv2[2];
    if (t == 0)  { float s = 0.f; for (int i = 0; i < FWW; i++) s += axv[i]; inv2[0] = 1.f / s; }
    if (t == 32) { float s = 0.f; for (int i = 0; i < FHH; i++) s += ayv[i]; inv2[1] = 1.f / s; }
    __syncthreads();

    float sc = inv2[0] * inv2[1];
    for (int p = t; p < NPAIR; p += 128) {
        int r = p / FWW;
        int c = p - r * FWW;
        g_wp[(size_t)b * NPAIR + p] = ayv[r] * axv[c] * sc;
    }
    for (int h = t; h < HD; h += 128)
        g_attn[(size_t)b * HD + h] = 0.f;
}

// ---------------------------------------------------------------------------
// Fused: blocks [0,128) run GEMM_C inp-half (SIMT fp32, wave 1 -> overlap);
// blocks [128, 128+2304) stream V (VSPLIT=18, PPB=64 = 2 warps).
// WTHR 1e-4 (calibrated rel_err ~6e-4). V loads __ldcs (zero reuse).
// ---------------------------------------------------------------------------
#define WTHR 1e-4f

__global__ void __launch_bounds__(256) fused_vred_gemm_kernel(
    const float* __restrict__ V,
    const float* __restrict__ inp, const float* __restrict__ Wc)
{
    __shared__ float sh[SHSZ];

    if (blockIdx.x < 128) {
        // ---- GEMM_C inp-half: k in [0,1024), 4 splits of 256, slots 0..3 ----
        int gb = blockIdx.x;
        int ks = gb >> 5;               // 0..3
        int r  = gb & 31;
        int n0 = (r & 15) << 6;
        int m0 = (r >> 4) << 6;
        gemm_body(inp, 1024, Wc, 2048,
                  g_pc + (size_t)ks * (B_SZ * 1024), 1024,
                  m0, n0, ks * 256, ks * 256 + 256, sh);
        return;
    }

    // ---- V reduction role ----
    int vb = blockIdx.x - 128;
    int b  = vb & 127;
    int p0 = (vb >> 7) * PPB;

    float* swc   = sh;                         // compacted weights [PPB]
    int*   sidxc = (int*)(sh + PPB);           // compacted indices [PPB]
    unsigned* smask = (unsigned*)(sh + 2*PPB); // per-warp ballot [2]
    int*   sbase = (int*)(sh + 2*PPB + 2);     // warp bases [2]
    int*   scnt  = (int*)(sh + 2*PPB + 4);

    int tid = threadIdx.x;
    float w = 0.f;
    if (tid < 64) {
        w = g_wp[(size_t)b * NPAIR + p0 + tid];
        unsigned m = __ballot_sync(0xffffffffu, w > WTHR);
        if ((tid & 31) == 0) smask[tid >> 5] = m;
    }
    __syncthreads();
    if (tid == 0) {
        int c0 = __popc(smask[0]);
        sbase[0] = 0; sbase[1] = c0;
        *scnt = c0 + __popc(smask[1]);
    }
    __syncthreads();
    if (tid < 64 && w > WTHR) {
        int lane = tid & 31, wp = tid >> 5;
        int pos = sbase[wp] + __popc(smask[wp] & ((1u << lane) - 1u));
        swc[pos]   = w;
        sidxc[pos] = tid;
    }
    __syncthreads();

    const int cnt = *scnt;
    if (cnt == 0) return;
    const int h0 = tid * 4;
    const float* vbase = V + ((size_t)p0 * B_SZ + b) * HD + h0;
    const size_t stride = (size_t)B_SZ * HD;

    float ax = 0.f, ay = 0.f, az = 0.f, aw = 0.f;
    int j = 0;
    for (; j + 8 <= cnt; j += 8) {
        float4 v[8];
        float  wv[8];
        #pragma unroll
        for (int q = 0; q < 8; q++) {
            wv[q] = swc[j + q];
            v[q]  = __ldcs((const float4*)(vbase + (size_t)sidxc[j + q] * stride));
        }
        #pragma unroll
        for (int q = 0; q < 8; q++) {
            ax += wv[q] * v[q].x; ay += wv[q] * v[q].y;
            az += wv[q] * v[q].z; aw += wv[q] * v[q].w;
        }
    }
    for (; j < cnt; j++) {
        float  wj = swc[j];
        float4 v  = __ldcs((const float4*)(vbase + (size_t)sidxc[j] * stride));
        ax += wj*v.x; ay += wj*v.y; az += wj*v.z; aw += wj*v.w;
    }

    float* ap = g_attn + (size_t)b * HD + h0;
    atomicAdd(ap + 0, ax);
    atomicAdd(ap + 1, ay);
    atomicAdd(ap + 2, az);
    atomicAdd(ap + 3, aw);
}

// ---------------------------------------------------------------------------
// GEMM_C attn-half (tf32 mma + cp.async) WITH FUSED EPILOGUE.
// k in [1024,2048), 8 splits of K=128, slots 4..11. grid (16 n, 2 m, 8 ks).
// The 8th (last) block per 64x64 tile sums all 12 partial slots + bc,
// applies relu, writes out, and resets the tile semaphore (graph-replay
// determinism). Partial-sum order over slots is fixed -> deterministic.
// ---------------------------------------------------------------------------
__global__ void __launch_bounds__(256) gemm_attn_kernel(
    const float* __restrict__ Wc, const float* __restrict__ bc,
    float* __restrict__ out)
{
    __shared__ float sh[MMSH];
    int ks = blockIdx.z;
    int m0 = blockIdx.y * 64;
    int n0 = blockIdx.x * 64;
    gemm_body_mma(g_attn, 1024, Wc + 1024, 2048,
                  g_pc + (size_t)(4 + ks) * (B_SZ * 1024), 1024,
                  m0, n0, ks * 128, ks * 128 + 128, sh);

    __threadfence();
    __shared__ int lastflag;
    int tileid = blockIdx.y * 16 + blockIdx.x;
    if (threadIdx.x == 0)
        lastflag = (atomicAdd(&g_sem[tileid], 1) == 7);
    __syncthreads();
    if (!lastflag) return;

    // Epilogue for this 64x64 tile: each thread does 1 row x 4 float4.
    int t   = threadIdx.x;
    int row = m0 + (t >> 2);
    int c4b = (n0 >> 2) + (t & 3) * 4;          // base float4 col
    #pragma unroll
    for (int q = 0; q < 4; q++) {
        int c4 = c4b + q;
        float4 a = ((const float4*)bc)[c4];
        #pragma unroll
        for (int s = 0; s < NSLOT; s++) {
            const float4* prow = (const float4*)
                (g_pc + (size_t)s * (B_SZ * 1024) + (size_t)row * 1024) + c4;
            float4 p = *prow;
            a.x += p.x; a.y += p.y; a.z += p.z; a.w += p.w;
        }
        a.x = fmaxf(a.x, 0.f); a.y = fmaxf(a.y, 0.f);
        a.z = fmaxf(a.z, 0.f); a.w = fmaxf(a.w, 0.f);
        ((float4*)out)[(size_t)row * 256 + c4] = a;
    }
    if (threadIdx.x == 0) g_sem[tileid] = 0;    // reset for next graph replay
}

// ---------------------------------------------------------------------------
extern "C" void kernel_launch(void* const* d_in, const int* in_sizes, int n_in,
                              void* d_out, int out_size)
{
    (void)in_sizes; (void)n_in; (void)out_size;
    const float* inp = (const float*)d_in[0];   // (128, 1024)
    const float* hid = (const float*)d_in[1];   // (128, 1024)
    const float* V   = (const float*)d_in[2];   // (24, 48, 128, 1024)
    const float* W1  = (const float*)d_in[3];   // (2048, 1024)
    const float* b1  = (const float*)d_in[4];   // (2048,)
    const float* W2  = (const float*)d_in[5];   // (2, 2048)
    const float* b2  = (const float*)d_in[6];   // (2,)
    const float* Wc  = (const float*)d_in[7];   // (1024, 2048)
    const float* bc  = (const float*)d_in[8];   // (1024,)
    float* out = (float*)d_out;                 // (128, 1024)

    gemm1_kernel<<<dim3(32, 2, 8), 256>>>(hid, W1);
    align_kernel<<<128, 128>>>(b1, W2, b2);
    fused_vred_gemm_kernel<<<128 + VBLKS, 256>>>(V, inp, Wc);
    gemm_attn_kernel<<<dim3(16, 2, 8), 256>>>(Wc, bc, out);
}

// round 17
// speedup vs baseline: 1.0902x; 1.0902x over previous
#include <cuda_runtime.h>
#include <math.h>
#include <stdint.h>

#define B_SZ   128
#define HD     1024
#define FHH    24
#define FWW    48
#define NPAIR  (FHH * FWW)       // 1152
#define VSPLIT 18
#define PPB    (NPAIR / VSPLIT)  // 64
#define VBLKS  (VSPLIT * B_SZ)   // 2304
#define NSLOT  12                // 4 inp-half + 8 attn-half split-K slots

// SIMT body smem (fused kernel)
#define SROW 68
#define SSTG (16 * SROW)
#define SHSZ (4 * SSTG)

// cp.async mma body smem: stage = A(64x16) + B(64x16), row stride 20 words
#define NST  4
#define AROW 20
#define ASTG (64 * AROW)         // 1280 words per operand stage
#define PSTG (2 * ASTG)          // 2560 words per stage
#define MMSH (NST * PSTG)        // 10240 words = 40 KB

// Scratch (device globals; no allocation allowed)
__device__ float g_p1[8 * B_SZ * 2048];        // GEMM1 split-K partials
__device__ float g_pc[NSLOT * B_SZ * 1024];    // GEMM_C split-K partials
__device__ float g_wp[B_SZ * NPAIR];           // normalized Gaussian weights
__device__ float g_attn[B_SZ * HD];            // attention output

// ---------------------------------------------------------------------------
// mma / cp.async helpers. tf32 operands are fed RAW fp32 bits — HMMA.TF32
// reads only the 19 tf32 bits (truncation rounding); validated in R16
// (rel_err delta ~4e-6). Removes all cvt.rna from the inner loop.
// ---------------------------------------------------------------------------
__device__ __forceinline__ void mma16x8x8(
    float& c0, float& c1, float& c2, float& c3,
    uint32_t a0, uint32_t a1, uint32_t a2, uint32_t a3,
    uint32_t b0, uint32_t b1)
{
    asm volatile(
        "mma.sync.aligned.m16n8k8.row.col.f32.tf32.tf32.f32 "
        "{%0,%1,%2,%3}, {%4,%5,%6,%7}, {%8,%9}, {%0,%1,%2,%3};"
        : "+f"(c0), "+f"(c1), "+f"(c2), "+f"(c3)
        : "r"(a0), "r"(a1), "r"(a2), "r"(a3), "r"(b0), "r"(b1));
}

__device__ __forceinline__ void cp16(uint32_t dst, const void* src) {
    asm volatile("cp.async.ca.shared.global [%0], [%1], 16;\n"
                 :: "r"(dst), "l"(src));
}
#define CP_COMMIT() asm volatile("cp.async.commit_group;\n" ::)
#define CP_WAIT2()  asm volatile("cp.async.wait_group 2;\n" ::)

// ---------------------------------------------------------------------------
// MMA (tf32) 64x64 tile GEMM, BK=16, 256 threads (8 warps: 4m x 2n),
// 4-stage cp.async pipeline (3 groups in flight). Raw fp32 in smem; raw-bit
// tf32 fragments (no cvt).
// ---------------------------------------------------------------------------
__device__ __forceinline__ void gemm_body_mma(
    const float* __restrict__ A,  int lda,
    const float* __restrict__ Bw, int ldb,
    float* __restrict__ outp,     int ldo,
    int m0, int n0, int kbeg, int kend, float* sh)
{
    const int t    = threadIdx.x;
    const int lane = t & 31;
    const int warp = t >> 5;
    const int gid  = lane >> 2;     // 0..7
    const int tig  = lane & 3;      // 0..3
    const int wm   = warp & 3;      // m tile: rows wm*16..+15
    const int wn   = warp >> 2;     // n tile: cols wn*32..+31
    const int lr   = t >> 2;        // 0..63 load row
    const int lc   = (t & 3) << 2;  // 0,4,8,12 load k

    const uint32_t sbase = (uint32_t)__cvta_generic_to_shared(sh);
    const float* Ap = A  + (size_t)(m0 + lr) * lda + lc;
    const float* Bp = Bw + (size_t)(n0 + lr) * ldb + lc;
    const int nch = (kend - kbeg) >> 4;

    auto issue = [&](int c) {
        if (c < nch) {
            int st = c & (NST - 1);
            uint32_t da = sbase + (uint32_t)(st * PSTG + lr * AROW + lc) * 4u;
            uint32_t db = da + (uint32_t)ASTG * 4u;
            int kn = kbeg + (c << 4);
            cp16(da, Ap + kn);
            cp16(db, Bp + kn);
        }
        CP_COMMIT();
    };

    issue(0); issue(1); issue(2);

    float acc[4][4] = {};   // [ntile][c0..c3]

    for (int c = 0; c < nch; c++) {
        CP_WAIT2();
        __syncthreads();

        const uint32_t* Ac = (const uint32_t*)(sh + (c & (NST - 1)) * PSTG);
        const uint32_t* Bc = Ac + ASTG;
        const int am0 = (wm * 16 + gid) * AROW;
        const int am1 = (wm * 16 + gid + 8) * AROW;

        #pragma unroll
        for (int ks = 0; ks < 2; ks++) {
            const int kk = ks << 3;
            uint32_t a0 = Ac[am0 + kk + tig];
            uint32_t a1 = Ac[am1 + kk + tig];
            uint32_t a2 = Ac[am0 + kk + tig + 4];
            uint32_t a3 = Ac[am1 + kk + tig + 4];
            #pragma unroll
            for (int nt = 0; nt < 4; nt++) {
                const int bn = (wn * 32 + nt * 8 + gid) * AROW;
                uint32_t b0 = Bc[bn + kk + tig];
                uint32_t b1 = Bc[bn + kk + tig + 4];
                mma16x8x8(acc[nt][0], acc[nt][1], acc[nt][2], acc[nt][3],
                          a0, a1, a2, a3, b0, b1);
            }
        }
        __syncthreads();
        issue(c + 3);
    }

    #pragma unroll
    for (int nt = 0; nt < 4; nt++) {
        float* orow = outp + (size_t)(m0 + wm*16 + gid) * ldo
                           + n0 + wn*32 + nt*8 + tig*2;
        *(float2*)orow              = make_float2(acc[nt][0], acc[nt][1]);
        *(float2*)(orow + 8 * ldo)  = make_float2(acc[nt][2], acc[nt][3]);
    }
}

// ---------------------------------------------------------------------------
// SIMT fp32 64x64 GEMM body (fused inp-half role; hidden under V stream).
// ---------------------------------------------------------------------------
__device__ __forceinline__ void gemm_body(
    const float* __restrict__ A,  int lda,
    const float* __restrict__ Bw, int ldb,
    float* __restrict__ outp,     int ldo,
    int m0, int n0, int kbeg, int kend, float* sh)
{
    const int t  = threadIdx.x;
    const int tx = t & 15;
    const int ty = t >> 4;
    const int lr = t >> 2;
    const int lc = (t & 3) << 2;

    float* As = sh;
    float* Bs = sh + 2 * SSTG;

    const float* Ap = A  + (size_t)(m0 + lr) * lda + lc;
    const float* Bp = Bw + (size_t)(n0 + lr) * ldb + lc;

    float4 ra = *(const float4*)(Ap + kbeg);
    float4 rb = *(const float4*)(Bp + kbeg);

    As[(lc+0)*SROW + lr] = ra.x;
    As[(lc+1)*SROW + lr] = ra.y;
    As[(lc+2)*SROW + lr] = ra.z;
    As[(lc+3)*SROW + lr] = ra.w;
    Bs[(lc+0)*SROW + lr] = rb.x;
    Bs[(lc+1)*SROW + lr] = rb.y;
    Bs[(lc+2)*SROW + lr] = rb.z;
    Bs[(lc+3)*SROW + lr] = rb.w;
    __syncthreads();

    float acc[4][4] = {};
    const int nch = (kend - kbeg) >> 4;

    for (int c = 0; c < nch; c++) {
        if (c + 1 < nch) {
            int kn = kbeg + ((c + 1) << 4);
            ra = *(const float4*)(Ap + kn);
            rb = *(const float4*)(Bp + kn);
        }
        const float* Ac = As + (c & 1) * SSTG;
        const float* Bc = Bs + (c & 1) * SSTG;
        #pragma unroll
        for (int kk = 0; kk < 16; kk++) {
            float4 av = *(const float4*)&Ac[kk * SROW + (ty << 2)];
            float4 bv = *(const float4*)&Bc[kk * SROW + (tx << 2)];
            float ar[4] = {av.x, av.y, av.z, av.w};
            float br[4] = {bv.x, bv.y, bv.z, bv.w};
            #pragma unroll
            for (int i = 0; i < 4; i++)
                #pragma unroll
                for (int j = 0; j < 4; j++)
                    acc[i][j] += ar[i] * br[j];
        }
        if (c + 1 < nch) {
            const int nx = ((c + 1) & 1) * SSTG;
            As[nx + (lc+0)*SROW + lr] = ra.x;
            As[nx + (lc+1)*SROW + lr] = ra.y;
            As[nx + (lc+2)*SROW + lr] = ra.z;
            As[nx + (lc+3)*SROW + lr] = ra.w;
            Bs[nx + (lc+0)*SROW + lr] = rb.x;
            Bs[nx + (lc+1)*SROW + lr] = rb.y;
            Bs[nx + (lc+2)*SROW + lr] = rb.z;
            Bs[nx + (lc+3)*SROW + lr] = rb.w;
            __syncthreads();
        }
    }

    #pragma unroll
    for (int i = 0; i < 4; i++) {
        float* orow = outp + (size_t)(m0 + (ty << 2) + i) * ldo + n0 + (tx << 2);
        *(float4*)orow = make_float4(acc[i][0], acc[i][1], acc[i][2], acc[i][3]);
    }
}

// ---------------------------------------------------------------------------
// GEMM1 (tf32 mma + cp.async): partials of hid @ W1^T.
// grid (32 n, 2 m, 8 ks), K=128 each.
// ---------------------------------------------------------------------------
__global__ void __launch_bounds__(256) gemm1_kernel(
    const float* __restrict__ hid, const float* __restrict__ W1)
{
    __shared__ float sh[MMSH];
    int ks = blockIdx.z;
    gemm_body_mma(hid, 1024, W1, 1024,
                  g_p1 + (size_t)ks * (B_SZ * 2048), 2048,
                  blockIdx.y * 64, blockIdx.x * 64,
                  ks * 128, ks * 128 + 128, sh);
}

// ---------------------------------------------------------------------------
// Align: t = tanh(sum 8 partials + b1); algn = sigmoid(t @ W2^T + b2);
// -> normalized separable Gaussian weights. Also zeros g_attn. grid 128.
// ---------------------------------------------------------------------------
__global__ void __launch_bounds__(128) align_kernel(
    const float* __restrict__ b1,
    const float* __restrict__ W2, const float* __restrict__ b2)
{
    int b = blockIdx.x;
    int t = threadIdx.x;

    float p0 = 0.f, p1 = 0.f;
    for (int n = t; n < 2048; n += 128) {
        float s = b1[n];
        #pragma unroll
        for (int sp = 0; sp < 8; sp++)
            s += g_p1[(size_t)sp * (B_SZ * 2048) + (size_t)b * 2048 + n];
        float tv = tanhf(s);
        p0 += tv * W2[n];
        p1 += tv * W2[2048 + n];
    }
    #pragma unroll
    for (int o = 16; o > 0; o >>= 1) {
        p0 += __shfl_down_sync(0xffffffffu, p0, o);
        p1 += __shfl_down_sync(0xffffffffu, p1, o);
    }
    __shared__ float r0[4], r1[4];
    int w = t >> 5, l = t & 31;
    if (l == 0) { r0[w] = p0; r1[w] = p1; }
    __syncthreads();

    __shared__ float cxy[2];
    if (t == 0) {
        float s0 = r0[0] + r0[1] + r0[2] + r0[3] + b2[0];
        float s1 = r1[0] + r1[1] + r1[2] + r1[3] + b2[1];
        cxy[0] = (1.f / (1.f + expf(-s0))) * (float)FWW;   // x0
        cxy[1] = (1.f / (1.f + expf(-s1))) * (float)FHH;   // y0
    }
    __syncthreads();

    __shared__ float axv[FWW], ayv[FHH];
    float x0 = cxy[0], y0 = cxy[1];
    if (t < FWW) { float d = (float)t - x0; axv[t] = expf(-d * d * (1.f / 32.f)); }
    if (t >= 64 && t < 64 + FHH) {
        int r = t - 64; float d = (float)r - y0; ayv[r] = expf(-d * d * (1.f / 32.f));
    }
    __syncthreads();

    __shared__ float inv2[2];
    if (t == 0)  { float s = 0.f; for (int i = 0; i < FWW; i++) s += axv[i]; inv2[0] = 1.f / s; }
    if (t == 32) { float s = 0.f; for (int i = 0; i < FHH; i++) s += ayv[i]; inv2[1] = 1.f / s; }
    __syncthreads();

    float sc = inv2[0] * inv2[1];
    for (int p = t; p < NPAIR; p += 128) {
        int r = p / FWW;
        int c = p - r * FWW;
        g_wp[(size_t)b * NPAIR + p] = ayv[r] * axv[c] * sc;
    }
    for (int h = t; h < HD; h += 128)
        g_attn[(size_t)b * HD + h] = 0.f;
}

// ---------------------------------------------------------------------------
// Fused: blocks [0,128) run GEMM_C inp-half (SIMT fp32, wave 1 -> overlap);
// blocks [128, 128+2304) stream V (VSPLIT=18, PPB=64 = 2 warps).
// WTHR 1e-4 (calibrated rel_err ~6e-4). V loads __ldcs (zero reuse).
// ---------------------------------------------------------------------------
#define WTHR 1e-4f

__global__ void __launch_bounds__(256) fused_vred_gemm_kernel(
    const float* __restrict__ V,
    const float* __restrict__ inp, const float* __restrict__ Wc)
{
    __shared__ float sh[SHSZ];

    if (blockIdx.x < 128) {
        // ---- GEMM_C inp-half: k in [0,1024), 4 splits of 256, slots 0..3 ----
        int gb = blockIdx.x;
        int ks = gb >> 5;               // 0..3
        int r  = gb & 31;
        int n0 = (r & 15) << 6;
        int m0 = (r >> 4) << 6;
        gemm_body(inp, 1024, Wc, 2048,
                  g_pc + (size_t)ks * (B_SZ * 1024), 1024,
                  m0, n0, ks * 256, ks * 256 + 256, sh);
        return;
    }

    // ---- V reduction role ----
    int vb = blockIdx.x - 128;
    int b  = vb & 127;
    int p0 = (vb >> 7) * PPB;

    float* swc   = sh;                         // compacted weights [PPB]
    int*   sidxc = (int*)(sh + PPB);           // compacted indices [PPB]
    unsigned* smask = (unsigned*)(sh + 2*PPB); // per-warp ballot [2]
    int*   sbase = (int*)(sh + 2*PPB + 2);     // warp bases [2]
    int*   scnt  = (int*)(sh + 2*PPB + 4);

    int tid = threadIdx.x;
    float w = 0.f;
    if (tid < 64) {
        w = g_wp[(size_t)b * NPAIR + p0 + tid];
        unsigned m = __ballot_sync(0xffffffffu, w > WTHR);
        if ((tid & 31) == 0) smask[tid >> 5] = m;
    }
    __syncthreads();
    if (tid == 0) {
        int c0 = __popc(smask[0]);
        sbase[0] = 0; sbase[1] = c0;
        *scnt = c0 + __popc(smask[1]);
    }
    __syncthreads();
    if (tid < 64 && w > WTHR) {
        int lane = tid & 31, wp = tid >> 5;
        int pos = sbase[wp] + __popc(smask[wp] & ((1u << lane) - 1u));
        swc[pos]   = w;
        sidxc[pos] = tid;
    }
    __syncthreads();

    const int cnt = *scnt;
    if (cnt == 0) return;
    const int h0 = tid * 4;
    const float* vbase = V + ((size_t)p0 * B_SZ + b) * HD + h0;
    const size_t stride = (size_t)B_SZ * HD;

    float ax = 0.f, ay = 0.f, az = 0.f, aw = 0.f;
    int j = 0;
    for (; j + 8 <= cnt; j += 8) {
        float4 v[8];
        float  wv[8];
        #pragma unroll
        for (int q = 0; q < 8; q++) {
            wv[q] = swc[j + q];
            v[q]  = __ldcs((const float4*)(vbase + (size_t)sidxc[j + q] * stride));
        }
        #pragma unroll
        for (int q = 0; q < 8; q++) {
            ax += wv[q] * v[q].x; ay += wv[q] * v[q].y;
            az += wv[q] * v[q].z; aw += wv[q] * v[q].w;
        }
    }
    for (; j < cnt; j++) {
        float  wj = swc[j];
        float4 v  = __ldcs((const float4*)(vbase + (size_t)sidxc[j] * stride));
        ax += wj*v.x; ay += wj*v.y; az += wj*v.z; aw += wj*v.w;
    }

    float* ap = g_attn + (size_t)b * HD + h0;
    atomicAdd(ap + 0, ax);
    atomicAdd(ap + 1, ay);
    atomicAdd(ap + 2, az);
    atomicAdd(ap + 3, aw);
}

// ---------------------------------------------------------------------------
// GEMM_C attn-half (tf32 mma + cp.async): k in [1024,2048), 8 splits of
// K=128 (measured-best), slots 4..11. grid (16 n, 2 m, 8 ks) = 256 blocks.
// ---------------------------------------------------------------------------
__global__ void __launch_bounds__(256) gemm_attn_kernel(const float* __restrict__ Wc)
{
    __shared__ float sh[MMSH];
    int ks = blockIdx.z;
    gemm_body_mma(g_attn, 1024, Wc + 1024, 2048,
                  g_pc + (size_t)(4 + ks) * (B_SZ * 1024), 1024,
                  blockIdx.y * 64, blockIdx.x * 64,
                  ks * 128, ks * 128 + 128, sh);
}

// ---------------------------------------------------------------------------
// Epilogue: out = relu(sum of 12 partials + bc). 32768 float4 elems.
// ---------------------------------------------------------------------------
__global__ void __launch_bounds__(256) epilogue_kernel(
    const float* __restrict__ bc, float* __restrict__ out)
{
    int idx = blockIdx.x * 256 + threadIdx.x;       // float4 index
    int col4 = idx & 255;
    float4 a = ((const float4*)bc)[col4];
    #pragma unroll
    for (int s = 0; s < NSLOT; s++) {
        float4 p = *(const float4*)(g_pc + (size_t)s * (B_SZ * 1024) + (size_t)idx * 4);
        a.x += p.x; a.y += p.y; a.z += p.z; a.w += p.w;
    }
    a.x = fmaxf(a.x, 0.f); a.y = fmaxf(a.y, 0.f);
    a.z = fmaxf(a.z, 0.f); a.w = fmaxf(a.w, 0.f);
    ((float4*)out)[idx] = a;
}

// ---------------------------------------------------------------------------
extern "C" void kernel_launch(void* const* d_in, const int* in_sizes, int n_in,
                              void* d_out, int out_size)
{
    (void)in_sizes; (void)n_in; (void)out_size;
    const float* inp = (const float*)d_in[0];   // (128, 1024)
    const float* hid = (const float*)d_in[1];   // (128, 1024)
    const float* V   = (const float*)d_in[2];   // (24, 48, 128, 1024)
    const float* W1  = (const float*)d_in[3];   // (2048, 1024)
    const float* b1  = (const float*)d_in[4];   // (2048,)
    const float* W2  = (const float*)d_in[5];   // (2, 2048)
    const float* b2  = (const float*)d_in[6];   // (2,)
    const float* Wc  = (const float*)d_in[7];   // (1024, 2048)
    const float* bc  = (const float*)d_in[8];   // (1024,)
    float* out = (float*)d_out;                 // (128, 1024)

    gemm1_kernel<<<dim3(32, 2, 8), 256>>>(hid, W1);
    align_kernel<<<128, 128>>>(b1, W2, b2);
    fused_vred_gemm_kernel<<<128 + VBLKS, 256>>>(V, inp, Wc);
    gemm_attn_kernel<<<dim3(16, 2, 8), 256>>>(Wc);
    epilogue_kernel<<<128, 256>>>(bc, out);
}